// round 9
// baseline (speedup 1.0000x reference)
#include <cuda_runtime.h>

// ConjunctionLayer: out[b,j] = -1/(-1 + sum_k log(1 - (1-x[b,k]) * W[j,k]))
// B=4096, D=512, N=128, fp32.
//
// sum(log Z) == log(prod Z), Z in (0.5, 1]: FMUL product chains, one log2 per
// 64 k's. Packed f32x2 math. 4-way K-split -> 2048 CTAs for occupancy; the
// last-arriving CTA of each b-tile (ticket counter) sums the 4 partial
// log2-sums from scratch and finalizes. Counters self-reset -> graph-safe.

#define Bdim 4096
#define Ddim 512
#define Ndim 128

#define KSPLIT 4
#define KQ     (Ddim / KSPLIT)   // 128 k's per CTA
#define TB     8                 // b-rows per tile
#define NTILE  (Bdim / TB)       // 512 tiles
#define KC     32                // k per staged chunk (128B rows)
#define NCH    (KQ / KC)         // 4 chunks per CTA
#define SROWX  36                // sx row stride (words)
#define XW     (TB * SROWX)      // 288 words
#define SWROW  32                // sw row stride (words), XOR-swizzled
#define BUFW   (XW + Ndim * SWROW)   // 4384 words / buffer

__device__ float g_partial[KSPLIT][Bdim * Ndim];   // 8MB partial log2 sums
__device__ int   g_cnt[NTILE];                     // arrival tickets (self-reset)

typedef unsigned long long ull;

__device__ __forceinline__ ull fma2(ull a, ull b, ull c) {
    ull d; asm("fma.rn.f32x2 %0, %1, %2, %3;" : "=l"(d) : "l"(a), "l"(b), "l"(c));
    return d;
}
__device__ __forceinline__ ull mul2(ull a, ull b) {
    ull d; asm("mul.rn.f32x2 %0, %1, %2;" : "=l"(d) : "l"(a), "l"(b));
    return d;
}
__device__ __forceinline__ void unpack2(ull v, float& lo, float& hi) {
    asm("mov.b64 {%0, %1}, %2;" : "=f"(lo), "=f"(hi) : "l"(v));
}
__device__ __forceinline__ void cp16(unsigned smem_dst, const void* gsrc) {
    asm volatile("cp.async.cg.shared.global [%0], [%1], 16;\n"
                 :: "r"(smem_dst), "l"(gsrc));
}

__global__ __launch_bounds__(128, 6)
void conj_kernel(const float* __restrict__ x,
                 const float* __restrict__ W,
                 float* __restrict__ out) {
    __shared__ float smem[2 * BUFW];
    __shared__ int s_last;

    const int tid   = threadIdx.x;
    const int tile  = blockIdx.x >> 2;
    const int ks    = blockIdx.x & 3;
    const int b_blk = tile * TB;
    const int kbase = ks * KQ;
    const int tj    = tid >> 2;               // 0..31 -> j group (j0 = 4*tj)
    const int tb    = tid & 3;                // 0..3  -> b rows tb, tb+4
    const int j0    = tj * 4;
    const int tj7   = tj & 7;                 // W swizzle key

    const ull ONE2 = 0x3F8000003F800000ull;   // {1.0f, 1.0f}

    ull   prod[2][4];
    float lsum[2][4];
#pragma unroll
    for (int r = 0; r < 2; r++)
#pragma unroll
        for (int c = 0; c < 4; c++) { prod[r][c] = ONE2; lsum[r][c] = 0.0f; }

    const unsigned sbase = (unsigned)__cvta_generic_to_shared(smem);

    // W staging: 1024 float4 per chunk, 8 per thread, XOR-swizzled column
    int wrow[8], wc4[8], wc4s[8];
#pragma unroll
    for (int t = 0; t < 8; t++) {
        int idx = tid + t * 128;
        wrow[t] = idx >> 3;
        wc4[t]  = idx & 7;
        wc4s[t] = wc4[t] ^ ((wrow[t] >> 2) & 7);
    }
    // x staging: 64 float4 per chunk via registers (a = x-1 folded), threads 0..63
    const int xrow = tid >> 3;
    const int xc4  = tid & 7;
    const bool xth = (tid < 64);

#define STAGE_W(CH, P)                                                        \
    do {                                                                      \
        int k0 = kbase + (CH) * KC;                                           \
        unsigned bofs = sbase + (P) * (BUFW * 4);                             \
        _Pragma("unroll")                                                     \
        for (int t = 0; t < 8; t++)                                           \
            cp16(bofs + (XW + wrow[t] * SWROW + wc4s[t] * 4) * 4,             \
                 &W[wrow[t] * Ddim + k0 + wc4[t] * 4]);                       \
        asm volatile("cp.async.commit_group;");                               \
    } while (0)

#define LDG_X(CH, DST)                                                        \
    do {                                                                      \
        if (xth) {                                                            \
            float4 v = *(const float4*)&x[(b_blk + xrow) * Ddim +             \
                                          kbase + (CH) * KC + xc4 * 4];       \
            (DST) = make_float4(v.x - 1.0f, v.y - 1.0f, v.z - 1.0f, v.w - 1.0f); \
        }                                                                     \
    } while (0)

#define STS_X(P, SRC)                                                         \
    do {                                                                      \
        if (xth)                                                              \
            *(float4*)&smem[(P) * BUFW + xrow * SROWX + xc4 * 4] = (SRC);     \
    } while (0)

    // prologue: x0 -> buf0, W0 in flight, x1 in regs
    float4 pxa, pxb;
    LDG_X(0, pxa);
    STS_X(0, pxa);
    STAGE_W(0, 0);
    LDG_X(1, pxa);

    for (int ch = 0; ch < NCH; ch++) {
        const int p = ch & 1;
        asm volatile("cp.async.wait_group 0;");
        __syncthreads();            // buf p complete (W + x); buf p^1 consumed

        if (ch + 1 < NCH) {
            STS_X(p ^ 1, pxa);
            STAGE_W(ch + 1, p ^ 1);
            if (ch + 2 < NCH) LDG_X(ch + 2, pxb);
        }

        const float* bx_s = &smem[p * BUFW];
        const float* bw_s = &smem[p * BUFW + XW + j0 * SWROW];

#pragma unroll
        for (int kk = 0; kk < KC; kk += 4) {
            ulonglong2 av0 = *(const ulonglong2*)&bx_s[tb * SROWX + kk];
            ulonglong2 av1 = *(const ulonglong2*)&bx_s[(tb + 4) * SROWX + kk];
            const float* wp = bw_s + ((((kk >> 2) ^ tj7) << 2));
#pragma unroll
            for (int c = 0; c < 4; c++) {
                ulonglong2 wv = *(const ulonglong2*)&wp[c * SWROW];
                prod[0][c] = mul2(prod[0][c], fma2((ull)av0.x, wv.x, ONE2));
                prod[0][c] = mul2(prod[0][c], fma2((ull)av0.y, wv.y, ONE2));
                prod[1][c] = mul2(prod[1][c], fma2((ull)av1.x, wv.x, ONE2));
                prod[1][c] = mul2(prod[1][c], fma2((ull)av1.y, wv.y, ONE2));
            }
        }

        if (ch & 1) {  // flush every 64 k's: merged product >= 0.5^64, normal
#pragma unroll
            for (int r = 0; r < 2; r++)
#pragma unroll
                for (int c = 0; c < 4; c++) {
                    float lo, hi;
                    unpack2(prod[r][c], lo, hi);
                    lsum[r][c] += __log2f(lo * hi);
                    prod[r][c] = ONE2;
                }
        }
        pxa = pxb;
    }

    // ---- write partial log2 sums for this K-quarter ----
    float* part = &g_partial[ks][0];
#pragma unroll
    for (int r = 0; r < 2; r++) {
        int b = b_blk + tb + r * 4;
        *(float4*)&part[b * Ndim + j0] =
            make_float4(lsum[r][0], lsum[r][1], lsum[r][2], lsum[r][3]);
    }

    // ---- last CTA of the tile finalizes ----
    __threadfence();
    __syncthreads();
    if (tid == 0)
        s_last = (atomicAdd(&g_cnt[tile], 1) == KSPLIT - 1);
    __syncthreads();

    if (s_last) {
        if (tid == 0) g_cnt[tile] = 0;     // self-reset for next launch
        const float LN2 = 0.6931471805599453f;
        // 1024 floats per tile, 8 per thread (two float4, same row)
        int f   = tid * 8;
        int row = f >> 7;
        int col = f & 127;
        int o   = (b_blk + row) * Ndim + col;
#pragma unroll
        for (int h = 0; h < 2; h++) {
            int oo = o + h * 4;
            float4 s0 = *(const float4*)&g_partial[0][oo];
            float4 s1 = *(const float4*)&g_partial[1][oo];
            float4 s2 = *(const float4*)&g_partial[2][oo];
            float4 s3 = *(const float4*)&g_partial[3][oo];
            float4 v;
            v.x = __fdividef(-1.0f, ((s0.x + s1.x) + (s2.x + s3.x)) * LN2 - 1.0f);
            v.y = __fdividef(-1.0f, ((s0.y + s1.y) + (s2.y + s3.y)) * LN2 - 1.0f);
            v.z = __fdividef(-1.0f, ((s0.z + s1.z) + (s2.z + s3.z)) * LN2 - 1.0f);
            v.w = __fdividef(-1.0f, ((s0.w + s1.w) + (s2.w + s3.w)) * LN2 - 1.0f);
            *(float4*)&out[oo] = v;
        }
    }
}

extern "C" void kernel_launch(void* const* d_in, const int* in_sizes, int n_in,
                              void* d_out, int out_size) {
    const float* x = (const float*)d_in[0];   // (4096, 512)
    const float* W = (const float*)d_in[1];   // (128, 512)
    float* out = (float*)d_out;               // (4096, 128)
    (void)in_sizes; (void)n_in; (void)out_size;

    conj_kernel<<<NTILE * KSPLIT, 128>>>(x, W, out);   // 2048 CTAs
}